// round 14
// baseline (speedup 1.0000x reference)
#include <cuda_runtime.h>
#include <cuda_bf16.h>
#include <cstdint>

// Problem constants
#define B       4
#define NSEQ    4096
#define DIM     1024
#define HEADS   8
#define DH      64
#define INNER   512          // HEADS*DH
#define M_ROWS  (B*NSEQ)     // 16384
#define N_QKV   (3*INNER)    // 1536
#define NCHUNK  8
#define ROWS_PER_CHUNK (NSEQ/NCHUNK)  // 512

// Scratch (device globals; no allocation allowed)
__device__ float g_qkv  [(size_t)M_ROWS * N_QKV];     // ~100.7 MB (row-major)
__device__ float g_ctxp [NCHUNK * B*HEADS * DH * DH]; // 4 MB
__device__ float g_attn [(size_t)M_ROWS * INNER];     // A-tiled, tf32
__device__ float g_xc   [(size_t)M_ROWS * DIM];       // A-tiled, tf32
__device__ float g_wqkvc[(size_t)N_QKV * DIM];        // B-tiled, tf32
__device__ float g_woutc[(size_t)DIM * INNER];        // B-tiled, tf32

// ---------------------------------------------------------------------------
__device__ __forceinline__ float to_tf32(float x) {
    uint32_t u;
    asm("cvt.rna.tf32.f32 %0, %1;" : "=r"(u) : "f"(x));
    return __uint_as_float(u);
}
__device__ __forceinline__ uint32_t smem_u32(const void* p) {
    uint32_t a;
    asm("{ .reg .u64 t; cvta.to.shared.u64 t, %1; cvt.u32.u64 %0, t; }"
        : "=r"(a) : "l"(p));
    return a;
}
#define CP_ASYNC16(dst, src) \
    asm volatile("cp.async.cg.shared.global [%0], [%1], 16;" \
                 :: "r"(dst), "l"(src) : "memory")
#define CP_COMMIT() asm volatile("cp.async.commit_group;" ::: "memory")
#define CP_WAIT2()  asm volatile("cp.async.wait_group 2;" ::: "memory")

__device__ __forceinline__ void mma_tf32(
    float& c0, float& c1, float& c2, float& c3,
    uint32_t a0, uint32_t a1, uint32_t a2, uint32_t a3,
    uint32_t b0, uint32_t b1)
{
    asm volatile(
        "mma.sync.aligned.m16n8k8.row.col.f32.tf32.tf32.f32 "
        "{%0,%1,%2,%3}, {%4,%5,%6,%7}, {%8,%9}, {%0,%1,%2,%3};"
        : "+f"(c0), "+f"(c1), "+f"(c2), "+f"(c3)
        : "r"(a0), "r"(a1), "r"(a2), "r"(a3), "r"(b0), "r"(b1));
}

// ---------------------------------------------------------------------------
// Tiled layouts (fragment-native for mma.m16n8k8.tf32):
//  A [M,K]: 16x8 block (R,S) at offset (R*(K/8)+S)*128; lane l owns floats
//    [4l..4l+3] = A[16R+g][8S+t], A[16R+g+8][8S+t], A[16R+g][8S+t+4],
//                 A[16R+g+8][8S+t+4]   (g=l>>2, t=l&3)
//  B [N,K]: 8x8 block (Rn,S) at offset (Rn*(K/8)+S)*64; lane l owns floats
//    [2l..2l+1] = Bm[8Rn+g][8S+t], Bm[8Rn+g][8S+t+4]
// ---------------------------------------------------------------------------
__global__ __launch_bounds__(256) void tile_a_kernel(
    const float* __restrict__ src, float* __restrict__ dst, int Mr, int Kc)
{
    int gid = blockIdx.x * 256 + threadIdx.x;
    int total = (Mr >> 4) * (Kc >> 3) * 32;
    if (gid >= total) return;
    int lane = gid & 31, blk = gid >> 5;
    int SB = Kc >> 3;
    int R = blk / SB, S = blk % SB;
    int g = lane >> 2, t = lane & 3;
    size_t r0 = (size_t)(R * 16 + g) * Kc + S * 8 + t;
    size_t r1 = r0 + (size_t)8 * Kc;
    float4 v;
    v.x = to_tf32(src[r0]);
    v.y = to_tf32(src[r1]);
    v.z = to_tf32(src[r0 + 4]);
    v.w = to_tf32(src[r1 + 4]);
    ((float4*)dst)[gid] = v;
}

__global__ __launch_bounds__(256) void tile_b_kernel(
    const float* __restrict__ src, float* __restrict__ dst, int Nr, int Kc)
{
    int gid = blockIdx.x * 256 + threadIdx.x;
    int total = (Nr >> 3) * (Kc >> 3) * 32;
    if (gid >= total) return;
    int lane = gid & 31, blk = gid >> 5;
    int SB = Kc >> 3;
    int Rn = blk / SB, S = blk % SB;
    int g = lane >> 2, t = lane & 3;
    size_t r0 = (size_t)(Rn * 8 + g) * Kc + S * 8 + t;
    float2 v;
    v.x = to_tf32(src[r0]);
    v.y = to_tf32(src[r0 + 4]);
    ((float2*)dst)[gid] = v;
}

// ---------------------------------------------------------------------------
// TF32 GEMM (NT): C[M,N] = A[M,K] @ Bm[N,K]^T (+ bias[N]), C row-major fp32.
// A in A-tiled layout, Bm in B-tiled layout (both pre-rounded tf32).
// CTA tile 128x256, 8 warps (2x4), warp 64x64. BK=32, 4-stage cp.async ring.
// Early producer issue + register double-buffered fragments.
// ---------------------------------------------------------------------------
#define BKQ 32
#define NSTAGE 4
#define A_ST_FLT (128*BKQ)                  // 4096 floats / stage (16 KB)
#define B_ST_FLT (256*BKQ)                  // 8192 floats / stage (32 KB)
#define OFF_A(s) ((s) * A_ST_FLT * 4)
#define OFF_B(s) (NSTAGE*A_ST_FLT*4 + (s) * B_ST_FLT * 4)
#define SMEM_GEMM (NSTAGE*(A_ST_FLT+B_ST_FLT)*4)   // 196608 B (192 KB)

__global__ __launch_bounds__(256) void tf32_gemm_mma(
    const float* __restrict__ A,
    const float* __restrict__ Bm,
    float* __restrict__ C,
    const float* __restrict__ bias,
    int M, int N, int K)
{
    extern __shared__ __align__(16) float smf[];
    const uint32_t sb = smem_u32(smf);
    const int tid  = threadIdx.x;
    const int wid  = tid >> 5;
    const int lane = tid & 31;
    const int g = lane >> 2, tg = lane & 3;
    const int bm = blockIdx.y * 128;
    const int bn = blockIdx.x * 256;
    const int wm = (wid >> 2) * 64;          // 0 or 64
    const int wn = (wid & 3) * 64;           // 0..192

    float acc[4][8][4];
    #pragma unroll
    for (int mi = 0; mi < 4; mi++)
        #pragma unroll
        for (int ni = 0; ni < 8; ni++)
            #pragma unroll
            for (int c = 0; c < 4; c++)
                acc[mi][ni][c] = 0.f;

    const int SB = K >> 3;                   // 8-wide k-blocks along K
    const float* Abase0 = A + ((size_t)(bm >> 4) * SB) * 128;
    const size_t AstrR  = (size_t)SB * 128;  // stride between M block-rows
    const float* Bbase0 = Bm + ((size_t)(bn >> 3) * SB) * 64;
    const size_t BstrR  = (size_t)SB * 64;   // stride between N blocks

    const int nk = K / BKQ;                  // chunks (4 k-blocks each)

    auto issue = [&](int kc, int buf) {
        const float* Ab = Abase0 + (size_t)kc * 4 * 128;
        const uint32_t ad = sb + OFF_A(buf);
        #pragma unroll
        for (int i = 0; i < 4; i++) {
            int f4  = tid + i * 256;          // 0..1023
            int flt = f4 << 2;
            int run = flt >> 9;               // block-row 0..7
            int win = flt & 511;
            CP_ASYNC16(ad + (uint32_t)f4 * 16, Ab + (size_t)run * AstrR + win);
        }
        const float* Bb = Bbase0 + (size_t)kc * 4 * 64;
        const uint32_t bd = sb + OFF_B(buf);
        #pragma unroll
        for (int i = 0; i < 8; i++) {
            int f4  = tid + i * 256;          // 0..2047
            int flt = f4 << 2;
            int run = flt >> 8;               // n-block 0..31
            int win = flt & 255;
            CP_ASYNC16(bd + (uint32_t)f4 * 16, Bb + (size_t)run * BstrR + win);
        }
        CP_COMMIT();
    };

    // prologue: 3 stages in flight
    issue(0, 0);
    if (nk > 1) issue(1, 1); else CP_COMMIT();
    if (nk > 2) issue(2, 2); else CP_COMMIT();

    const int abr = wm >> 4;                  // first A block-row (0 or 4)
    const int bbr = wn >> 3;                  // first B n-block (0..24)

    for (int kc = 0; kc < nk; kc++) {
        CP_WAIT2();
        __syncthreads();

        // early producer: slot (kc+3)%4 == (kc-1)%4, fully consumed in
        // chunk kc-1; all warps passed the barrier above, so safe now.
        if (kc + 3 < nk) issue(kc + 3, (kc + 3) & (NSTAGE - 1));
        else CP_COMMIT();                      // keep group accounting uniform

        const int cur = kc & (NSTAGE - 1);
        const float* As = smf + OFF_A(cur) / 4;
        const float* Bs = smf + OFF_B(cur) / 4;

        // register double-buffered fragments across ks-steps
        uint32_t af[2][4][4];
        uint32_t bf[2][8][2];

        auto load_frags = [&](int ks, uint32_t (*afb)[4], uint32_t (*bfb)[2]) {
            #pragma unroll
            for (int mi = 0; mi < 4; mi++) {
                float4 v = *(const float4*)(
                    As + ((abr + mi) * 4 + ks) * 128 + lane * 4);
                afb[mi][0] = __float_as_uint(v.x);
                afb[mi][1] = __float_as_uint(v.y);
                afb[mi][2] = __float_as_uint(v.z);
                afb[mi][3] = __float_as_uint(v.w);
            }
            #pragma unroll
            for (int ni = 0; ni < 8; ni++) {
                float2 v = *(const float2*)(
                    Bs + ((bbr + ni) * 4 + ks) * 64 + lane * 2);
                bfb[ni][0] = __float_as_uint(v.x);
                bfb[ni][1] = __float_as_uint(v.y);
            }
        };

        load_frags(0, af[0], bf[0]);
        #pragma unroll
        for (int ks = 0; ks < 4; ks++) {
            const int cb = ks & 1;
            if (ks < 3) load_frags(ks + 1, af[cb ^ 1], bf[cb ^ 1]);
            #pragma unroll
            for (int mi = 0; mi < 4; mi++)
                #pragma unroll
                for (int ni = 0; ni < 8; ni++)
                    mma_tf32(acc[mi][ni][0], acc[mi][ni][1],
                             acc[mi][ni][2], acc[mi][ni][3],
                             af[cb][mi][0], af[cb][mi][1],
                             af[cb][mi][2], af[cb][mi][3],
                             bf[cb][ni][0], bf[cb][ni][1]);
        }
    }

    // epilogue: c0/c1 at (row g, cols 2t,2t+1); c2/c3 at (row g+8)
    #pragma unroll
    for (int ni = 0; ni < 8; ni++) {
        const int col = bn + wn + ni * 8 + tg * 2;
        float b0 = 0.f, b1 = 0.f;
        if (bias) { b0 = bias[col]; b1 = bias[col + 1]; }
        #pragma unroll
        for (int mi = 0; mi < 4; mi++) {
            const int r0 = bm + wm + mi * 16 + g;
            *(float2*)&C[(size_t)r0 * N + col] =
                make_float2(acc[mi][ni][0] + b0, acc[mi][ni][1] + b1);
            *(float2*)&C[(size_t)(r0 + 8) * N + col] =
                make_float2(acc[mi][ni][2] + b0, acc[mi][ni][3] + b1);
        }
    }
}

// ---------------------------------------------------------------------------
// Context kernel: ctx[d][e] = sum_n softmax(k[n,:])[d] * v[n,e], split-K
// ---------------------------------------------------------------------------
__global__ __launch_bounds__(256) void ctx_kernel()
{
    const int pair  = blockIdx.x;
    const int chunk = blockIdx.y;
    const int b = pair >> 3, h = pair & 7;
    const int tid = threadIdx.x;

    __shared__ __align__(16) float sk[32][DH];
    __shared__ __align__(16) float sv[32][DH];

    const int d0 = (tid >> 4) * 4;
    const int e0 = (tid & 15) * 4;

    float acc[4][4];
    #pragma unroll
    for (int i = 0; i < 4; i++)
        #pragma unroll
        for (int j = 0; j < 4; j++) acc[i][j] = 0.f;

    const float* base = g_qkv + (size_t)b * NSEQ * N_QKV;
    const int n_begin = chunk * ROWS_PER_CHUNK;

    for (int n0 = n_begin; n0 < n_begin + ROWS_PER_CHUNK; n0 += 32) {
        #pragma unroll
        for (int i = 0; i < 2; i++) {
            int id = tid + i * 256;
            int r  = id >> 4;
            int c  = (id & 15) * 4;
            size_t off = (size_t)(n0 + r) * N_QKV + h * DH + c;
            *(float4*)&sk[r][c] = *(const float4*)(base + off + INNER);
            *(float4*)&sv[r][c] = *(const float4*)(base + off + 2 * INNER);
        }
        __syncthreads();

        {
            int r     = tid >> 3;
            int lane8 = tid & 7;
            float vals[8];
            float m = -1e30f;
            #pragma unroll
            for (int j = 0; j < 8; j++) {
                vals[j] = sk[r][lane8 * 8 + j];
                m = fmaxf(m, vals[j]);
            }
            #pragma unroll
            for (int s = 4; s >= 1; s >>= 1)
                m = fmaxf(m, __shfl_xor_sync(0xffffffffu, m, s));
            float sum = 0.f;
            #pragma unroll
            for (int j = 0; j < 8; j++) { vals[j] = __expf(vals[j] - m); sum += vals[j]; }
            #pragma unroll
            for (int s = 4; s >= 1; s >>= 1)
                sum += __shfl_xor_sync(0xffffffffu, sum, s);
            float inv = 1.0f / sum;
            #pragma unroll
            for (int j = 0; j < 8; j++)
                sk[r][lane8 * 8 + j] = vals[j] * inv;
        }
        __syncthreads();

        #pragma unroll 4
        for (int r = 0; r < 32; r++) {
            float4 kd = *(const float4*)&sk[r][d0];
            float4 ve = *(const float4*)&sv[r][e0];
            float kdv[4] = {kd.x, kd.y, kd.z, kd.w};
            float vev[4] = {ve.x, ve.y, ve.z, ve.w};
            #pragma unroll
            for (int i = 0; i < 4; i++)
                #pragma unroll
                for (int j = 0; j < 4; j++)
                    acc[i][j] += kdv[i] * vev[j];
        }
        __syncthreads();
    }

    float* out = g_ctxp + ((size_t)chunk * (B*HEADS) + pair) * DH * DH;
    #pragma unroll
    for (int i = 0; i < 4; i++) {
        float4 v = make_float4(acc[i][0], acc[i][1], acc[i][2], acc[i][3]);
        *(float4*)&out[(d0 + i) * DH + e0] = v;
    }
}

// ---------------------------------------------------------------------------
// Attention-apply; writes g_attn in A-tiled tf32 layout (feeds GEMM4)
// ---------------------------------------------------------------------------
__global__ __launch_bounds__(256) void attn_kernel()
{
    const int pair = blockIdx.x;
    const int b = pair >> 3, h = pair & 7;
    const int n0 = blockIdx.y * 128;
    const int tid = threadIdx.x;

    __shared__ __align__(16) float sctx[DH][DH];
    __shared__ __align__(16) float sq[128][DH];

    for (int idx = tid; idx < DH * DH; idx += 256) {
        float s = 0.f;
        #pragma unroll
        for (int ch = 0; ch < NCHUNK; ch++)
            s += g_ctxp[((size_t)ch * (B*HEADS) + pair) * DH * DH + idx];
        sctx[idx >> 6][idx & 63] = s;
    }

    const float* qbase = g_qkv + (size_t)b * NSEQ * N_QKV + h * DH;
    #pragma unroll
    for (int i = 0; i < 8; i++) {
        int id = tid + i * 256;
        int r  = id >> 4;
        int c  = (id & 15) * 4;
        *(float4*)&sq[r][c] =
            *(const float4*)(qbase + (size_t)(n0 + r) * N_QKV + c);
    }
    __syncthreads();

    const int e0 = (tid & 15) * 4;
    const int rg = tid >> 4;
    float acc[8][4];
    #pragma unroll
    for (int i = 0; i < 8; i++)
        #pragma unroll
        for (int j = 0; j < 4; j++) acc[i][j] = 0.f;

    #pragma unroll 8
    for (int d = 0; d < DH; d++) {
        float4 c4 = *(const float4*)&sctx[d][e0];
        float cv[4] = {c4.x, c4.y, c4.z, c4.w};
        #pragma unroll
        for (int i = 0; i < 8; i++) {
            float a = sq[rg + 16 * i][d];
            #pragma unroll
            for (int j = 0; j < 4; j++)
                acc[i][j] += a * cv[j];
        }
    }

    // tiled store: row = b*NSEQ + n0 + rg + 16*i, col = h*64 + e0 + j
    const int R0 = (b * NSEQ + n0) >> 4;          // + i
    const int S  = (h * DH + e0) >> 3;
    const int g2 = rg & 7;
    const int slot = (rg >> 3) + ((e0 & 4) ? 2 : 0);
    #pragma unroll
    for (int i = 0; i < 8; i++) {
        float* blk = g_attn + ((size_t)(R0 + i) * (INNER >> 3) + S) * 128;
        #pragma unroll
        for (int j = 0; j < 4; j++)
            blk[(g2 * 4 + j) * 4 + slot] = to_tf32(acc[i][j]);
    }
}

// ---------------------------------------------------------------------------
extern "C" void kernel_launch(void* const* d_in, const int* in_sizes, int n_in,
                              void* d_out, int out_size)
{
    const float* x     = (const float*)d_in[0];   // [4,4096,1024]
    const float* w_qkv = (const float*)d_in[1];   // [1536,1024]
    const float* w_out = (const float*)d_in[2];   // [1024,512]
    const float* b_out = (const float*)d_in[3];   // [1024]
    float* out = (float*)d_out;                   // [4,4096,1024]

    float *qkv_p, *attn_p, *xc_p, *wqkvc_p, *woutc_p;
    cudaGetSymbolAddress((void**)&qkv_p,   g_qkv);
    cudaGetSymbolAddress((void**)&attn_p,  g_attn);
    cudaGetSymbolAddress((void**)&xc_p,    g_xc);
    cudaGetSymbolAddress((void**)&wqkvc_p, g_wqkvc);
    cudaGetSymbolAddress((void**)&woutc_p, g_woutc);

    cudaFuncSetAttribute(tf32_gemm_mma,
        cudaFuncAttributeMaxDynamicSharedMemorySize, SMEM_GEMM);

    // 0) tile + round inputs to fragment-native tf32 layouts
    {
        int ta = (M_ROWS / 16) * (DIM / 8) * 32;
        tile_a_kernel<<<(ta + 255) / 256, 256>>>(x, xc_p, M_ROWS, DIM);
        int tb1 = (N_QKV / 8) * (DIM / 8) * 32;
        tile_b_kernel<<<(tb1 + 255) / 256, 256>>>(w_qkv, wqkvc_p, N_QKV, DIM);
        int tb2 = (DIM / 8) * (INNER / 8) * 32;
        tile_b_kernel<<<(tb2 + 255) / 256, 256>>>(w_out, woutc_p, DIM, INNER);
    }

    // 1) QKV projection: [16384,1536] = xc @ wqkvc^T
    tf32_gemm_mma<<<dim3(N_QKV / 256, M_ROWS / 128), 256, SMEM_GEMM>>>(
        xc_p, wqkvc_p, qkv_p, nullptr, M_ROWS, N_QKV, DIM);

    // 2) softmax(k) + context partials
    ctx_kernel<<<dim3(B * HEADS, NCHUNK), 256>>>();

    // 3) q @ context -> attn (tiled tf32) [16384, 512]
    attn_kernel<<<dim3(B * HEADS, NSEQ / 128), 256>>>();

    // 4) output projection + bias: [16384,1024] = attn @ woutc^T + b_out
    tf32_gemm_mma<<<dim3(DIM / 256, M_ROWS / 128), 256, SMEM_GEMM>>>(
        attn_p, woutc_p, out, b_out, M_ROWS, DIM, INNER);
}

// round 15
// speedup vs baseline: 1.0546x; 1.0546x over previous
#include <cuda_runtime.h>
#include <cuda_bf16.h>
#include <cstdint>

// Problem constants
#define B       4
#define NSEQ    4096
#define DIM     1024
#define HEADS   8
#define DH      64
#define INNER   512          // HEADS*DH
#define M_ROWS  (B*NSEQ)     // 16384
#define N_QKV   (3*INNER)    // 1536
#define NCHUNK  8
#define ROWS_PER_CHUNK (NSEQ/NCHUNK)  // 512

// Scratch (device globals; no allocation allowed)
__device__ float g_qkv  [(size_t)M_ROWS * N_QKV];     // ~100.7 MB (row-major)
__device__ float g_ctxp [NCHUNK * B*HEADS * DH * DH]; // 4 MB
__device__ float g_attn [(size_t)M_ROWS * INNER];     // A-tiled, tf32
__device__ float g_xc   [(size_t)M_ROWS * DIM];       // A-tiled, tf32
__device__ float g_wqkvc[(size_t)N_QKV * DIM];        // B-tiled, tf32
__device__ float g_woutc[(size_t)DIM * INNER];        // B-tiled, tf32

// ---------------------------------------------------------------------------
__device__ __forceinline__ float to_tf32(float x) {
    uint32_t u;
    asm("cvt.rna.tf32.f32 %0, %1;" : "=r"(u) : "f"(x));
    return __uint_as_float(u);
}
__device__ __forceinline__ uint32_t smem_u32(const void* p) {
    uint32_t a;
    asm("{ .reg .u64 t; cvta.to.shared.u64 t, %1; cvt.u32.u64 %0, t; }"
        : "=r"(a) : "l"(p));
    return a;
}
#define CP_ASYNC16(dst, src) \
    asm volatile("cp.async.cg.shared.global [%0], [%1], 16;" \
                 :: "r"(dst), "l"(src) : "memory")
#define CP_COMMIT() asm volatile("cp.async.commit_group;" ::: "memory")
#define CP_WAIT2()  asm volatile("cp.async.wait_group 2;" ::: "memory")

__device__ __forceinline__ void mma_tf32(
    float& c0, float& c1, float& c2, float& c3,
    uint32_t a0, uint32_t a1, uint32_t a2, uint32_t a3,
    uint32_t b0, uint32_t b1)
{
    asm volatile(
        "mma.sync.aligned.m16n8k8.row.col.f32.tf32.tf32.f32 "
        "{%0,%1,%2,%3}, {%4,%5,%6,%7}, {%8,%9}, {%0,%1,%2,%3};"
        : "+f"(c0), "+f"(c1), "+f"(c2), "+f"(c3)
        : "r"(a0), "r"(a1), "r"(a2), "r"(a3), "r"(b0), "r"(b1));
}

// ---------------------------------------------------------------------------
// Tiled layouts (fragment-native for mma.m16n8k8.tf32):
//  A [M,K]: 16x8 block (R,S) at offset (R*(K/8)+S)*128; lane l owns floats
//    [4l..4l+3] = A[16R+g][8S+t], A[16R+g+8][8S+t], A[16R+g][8S+t+4],
//                 A[16R+g+8][8S+t+4]   (g=l>>2, t=l&3)
//  B [N,K]: 8x8 block (Rn,S) at offset (Rn*(K/8)+S)*64; lane l owns floats
//    [2l..2l+1] = Bm[8Rn+g][8S+t], Bm[8Rn+g][8S+t+4]
// ---------------------------------------------------------------------------
__global__ __launch_bounds__(256) void tile_a_kernel(
    const float* __restrict__ src, float* __restrict__ dst, int Mr, int Kc)
{
    int gid = blockIdx.x * 256 + threadIdx.x;
    int total = (Mr >> 4) * (Kc >> 3) * 32;
    if (gid >= total) return;
    int lane = gid & 31, blk = gid >> 5;
    int SB = Kc >> 3;
    int R = blk / SB, S = blk % SB;
    int g = lane >> 2, t = lane & 3;
    size_t r0 = (size_t)(R * 16 + g) * Kc + S * 8 + t;
    size_t r1 = r0 + (size_t)8 * Kc;
    float4 v;
    v.x = to_tf32(src[r0]);
    v.y = to_tf32(src[r1]);
    v.z = to_tf32(src[r0 + 4]);
    v.w = to_tf32(src[r1 + 4]);
    ((float4*)dst)[gid] = v;
}

__global__ __launch_bounds__(256) void tile_b_kernel(
    const float* __restrict__ src, float* __restrict__ dst, int Nr, int Kc)
{
    int gid = blockIdx.x * 256 + threadIdx.x;
    int total = (Nr >> 3) * (Kc >> 3) * 32;
    if (gid >= total) return;
    int lane = gid & 31, blk = gid >> 5;
    int SB = Kc >> 3;
    int Rn = blk / SB, S = blk % SB;
    int g = lane >> 2, t = lane & 3;
    size_t r0 = (size_t)(Rn * 8 + g) * Kc + S * 8 + t;
    float2 v;
    v.x = to_tf32(src[r0]);
    v.y = to_tf32(src[r0 + 4]);
    ((float2*)dst)[gid] = v;
}

// ---------------------------------------------------------------------------
// TF32 GEMM (NT): C[M,N] = A[M,K] @ Bm[N,K]^T (+ bias[N]), C row-major fp32.
// A in A-tiled layout, Bm in B-tiled layout (both pre-rounded tf32).
// CTA tile 128 x TILE_N, 8 warps (2x4), warp 64 x (TILE_N/4).
// BK=32, 4-stage cp.async ring. TILE_N in {128, 192} for tail efficiency.
// ---------------------------------------------------------------------------
#define BKQ 32
#define NSTAGE 4
#define A_ST_FLT (128*BKQ)                   // 4096 floats / stage (16 KB)

template<int TILE_N>
__global__ __launch_bounds__(256) void tf32_gemm_mma(
    const float* __restrict__ A,
    const float* __restrict__ Bm,
    float* __restrict__ C,
    const float* __restrict__ bias,
    int M, int N, int K)
{
    constexpr int B_ST_FLT = TILE_N * BKQ;   // floats / stage
    constexpr int NBW = TILE_N / 32;         // n-blocks per warp (4 or 6)
    constexpr int BF4T = B_ST_FLT / 4 / 256; // B float4 per thread (4 or 6)

    extern __shared__ __align__(16) float smf[];
    const uint32_t sb = smem_u32(smf);
    const int tid  = threadIdx.x;
    const int wid  = tid >> 5;
    const int lane = tid & 31;
    const int g = lane >> 2, tg = lane & 3;
    const int bm = blockIdx.y * 128;
    const int bn = blockIdx.x * TILE_N;
    const int wm = (wid >> 2) * 64;                  // 0 or 64
    const int wn = (wid & 3) * (TILE_N / 4);         // warp n offset

    auto OFF_A = [&](int s) { return s * A_ST_FLT * 4; };
    auto OFF_B = [&](int s) { return NSTAGE * A_ST_FLT * 4 + s * B_ST_FLT * 4; };

    float acc[4][NBW][4];
    #pragma unroll
    for (int mi = 0; mi < 4; mi++)
        #pragma unroll
        for (int ni = 0; ni < NBW; ni++)
            #pragma unroll
            for (int c = 0; c < 4; c++)
                acc[mi][ni][c] = 0.f;

    const int SB = K >> 3;                   // 8-wide k-blocks along K
    const float* Abase0 = A + ((size_t)(bm >> 4) * SB) * 128;
    const size_t AstrR  = (size_t)SB * 128;  // stride between M block-rows
    const float* Bbase0 = Bm + ((size_t)(bn >> 3) * SB) * 64;
    const size_t BstrR  = (size_t)SB * 64;   // stride between N blocks

    const int nk = K / BKQ;                  // chunks (4 k-blocks each)

    auto issue = [&](int kc, int buf) {
        const float* Ab = Abase0 + (size_t)kc * 4 * 128;
        const uint32_t ad = sb + OFF_A(buf);
        #pragma unroll
        for (int i = 0; i < 4; i++) {
            int f4  = tid + i * 256;          // 0..1023
            int flt = f4 << 2;
            int run = flt >> 9;               // block-row 0..7
            int win = flt & 511;
            CP_ASYNC16(ad + (uint32_t)f4 * 16, Ab + (size_t)run * AstrR + win);
        }
        const float* Bb = Bbase0 + (size_t)kc * 4 * 64;
        const uint32_t bd = sb + OFF_B(buf);
        #pragma unroll
        for (int i = 0; i < BF4T; i++) {
            int f4  = tid + i * 256;
            int flt = f4 << 2;
            int run = flt >> 8;               // n-block
            int win = flt & 255;
            CP_ASYNC16(bd + (uint32_t)f4 * 16, Bb + (size_t)run * BstrR + win);
        }
        CP_COMMIT();
    };

    // prologue: 3 stages in flight
    issue(0, 0);
    if (nk > 1) issue(1, 1); else CP_COMMIT();
    if (nk > 2) issue(2, 2); else CP_COMMIT();

    const int abr = wm >> 4;                  // first A block-row (0 or 4)
    const int bbr = wn >> 3;                  // first B n-block

    for (int kc = 0; kc < nk; kc++) {
        CP_WAIT2();
        __syncthreads();

        // early producer: slot (kc+3)%4 was fully consumed in chunk kc-1
        if (kc + 3 < nk) issue(kc + 3, (kc + 3) & (NSTAGE - 1));
        else CP_COMMIT();                      // keep group accounting uniform

        const int cur = kc & (NSTAGE - 1);
        const float* As = smf + OFF_A(cur) / 4;
        const float* Bs = smf + OFF_B(cur) / 4;

        #pragma unroll
        for (int ks = 0; ks < 4; ks++) {
            uint32_t af[4][4];
            #pragma unroll
            for (int mi = 0; mi < 4; mi++) {
                float4 v = *(const float4*)(
                    As + ((abr + mi) * 4 + ks) * 128 + lane * 4);
                af[mi][0] = __float_as_uint(v.x);
                af[mi][1] = __float_as_uint(v.y);
                af[mi][2] = __float_as_uint(v.z);
                af[mi][3] = __float_as_uint(v.w);
            }
            uint32_t bf[NBW][2];
            #pragma unroll
            for (int ni = 0; ni < NBW; ni++) {
                float2 v = *(const float2*)(
                    Bs + ((bbr + ni) * 4 + ks) * 64 + lane * 2);
                bf[ni][0] = __float_as_uint(v.x);
                bf[ni][1] = __float_as_uint(v.y);
            }
            #pragma unroll
            for (int mi = 0; mi < 4; mi++)
                #pragma unroll
                for (int ni = 0; ni < NBW; ni++)
                    mma_tf32(acc[mi][ni][0], acc[mi][ni][1],
                             acc[mi][ni][2], acc[mi][ni][3],
                             af[mi][0], af[mi][1], af[mi][2], af[mi][3],
                             bf[ni][0], bf[ni][1]);
        }
    }

    // epilogue: c0/c1 at (row g, cols 2t,2t+1); c2/c3 at (row g+8)
    #pragma unroll
    for (int ni = 0; ni < NBW; ni++) {
        const int col = bn + wn + ni * 8 + tg * 2;
        float b0 = 0.f, b1 = 0.f;
        if (bias) { b0 = bias[col]; b1 = bias[col + 1]; }
        #pragma unroll
        for (int mi = 0; mi < 4; mi++) {
            const int r0 = bm + wm + mi * 16 + g;
            *(float2*)&C[(size_t)r0 * N + col] =
                make_float2(acc[mi][ni][0] + b0, acc[mi][ni][1] + b1);
            *(float2*)&C[(size_t)(r0 + 8) * N + col] =
                make_float2(acc[mi][ni][2] + b0, acc[mi][ni][3] + b1);
        }
    }
}

#define SMEM_GEMM_N(TN) (NSTAGE * (A_ST_FLT + (TN) * BKQ) * 4)

// ---------------------------------------------------------------------------
// Context kernel: ctx[d][e] = sum_n softmax(k[n,:])[d] * v[n,e], split-K
// ---------------------------------------------------------------------------
__global__ __launch_bounds__(256) void ctx_kernel()
{
    const int pair  = blockIdx.x;
    const int chunk = blockIdx.y;
    const int b = pair >> 3, h = pair & 7;
    const int tid = threadIdx.x;

    __shared__ __align__(16) float sk[32][DH];
    __shared__ __align__(16) float sv[32][DH];

    const int d0 = (tid >> 4) * 4;
    const int e0 = (tid & 15) * 4;

    float acc[4][4];
    #pragma unroll
    for (int i = 0; i < 4; i++)
        #pragma unroll
        for (int j = 0; j < 4; j++) acc[i][j] = 0.f;

    const float* base = g_qkv + (size_t)b * NSEQ * N_QKV;
    const int n_begin = chunk * ROWS_PER_CHUNK;

    for (int n0 = n_begin; n0 < n_begin + ROWS_PER_CHUNK; n0 += 32) {
        #pragma unroll
        for (int i = 0; i < 2; i++) {
            int id = tid + i * 256;
            int r  = id >> 4;
            int c  = (id & 15) * 4;
            size_t off = (size_t)(n0 + r) * N_QKV + h * DH + c;
            *(float4*)&sk[r][c] = *(const float4*)(base + off + INNER);
            *(float4*)&sv[r][c] = *(const float4*)(base + off + 2 * INNER);
        }
        __syncthreads();

        {
            int r     = tid >> 3;
            int lane8 = tid & 7;
            float vals[8];
            float m = -1e30f;
            #pragma unroll
            for (int j = 0; j < 8; j++) {
                vals[j] = sk[r][lane8 * 8 + j];
                m = fmaxf(m, vals[j]);
            }
            #pragma unroll
            for (int s = 4; s >= 1; s >>= 1)
                m = fmaxf(m, __shfl_xor_sync(0xffffffffu, m, s));
            float sum = 0.f;
            #pragma unroll
            for (int j = 0; j < 8; j++) { vals[j] = __expf(vals[j] - m); sum += vals[j]; }
            #pragma unroll
            for (int s = 4; s >= 1; s >>= 1)
                sum += __shfl_xor_sync(0xffffffffu, sum, s);
            float inv = 1.0f / sum;
            #pragma unroll
            for (int j = 0; j < 8; j++)
                sk[r][lane8 * 8 + j] = vals[j] * inv;
        }
        __syncthreads();

        #pragma unroll 4
        for (int r = 0; r < 32; r++) {
            float4 kd = *(const float4*)&sk[r][d0];
            float4 ve = *(const float4*)&sv[r][e0];
            float kdv[4] = {kd.x, kd.y, kd.z, kd.w};
            float vev[4] = {ve.x, ve.y, ve.z, ve.w};
            #pragma unroll
            for (int i = 0; i < 4; i++)
                #pragma unroll
                for (int j = 0; j < 4; j++)
                    acc[i][j] += kdv[i] * vev[j];
        }
        __syncthreads();
    }

    float* out = g_ctxp + ((size_t)chunk * (B*HEADS) + pair) * DH * DH;
    #pragma unroll
    for (int i = 0; i < 4; i++) {
        float4 v = make_float4(acc[i][0], acc[i][1], acc[i][2], acc[i][3]);
        *(float4*)&out[(d0 + i) * DH + e0] = v;
    }
}

// ---------------------------------------------------------------------------
// Attention-apply; writes g_attn in A-tiled tf32 layout (feeds GEMM4)
// ---------------------------------------------------------------------------
__global__ __launch_bounds__(256) void attn_kernel()
{
    const int pair = blockIdx.x;
    const int b = pair >> 3, h = pair & 7;
    const int n0 = blockIdx.y * 128;
    const int tid = threadIdx.x;

    __shared__ __align__(16) float sctx[DH][DH];
    __shared__ __align__(16) float sq[128][DH];

    for (int idx = tid; idx < DH * DH; idx += 256) {
        float s = 0.f;
        #pragma unroll
        for (int ch = 0; ch < NCHUNK; ch++)
            s += g_ctxp[((size_t)ch * (B*HEADS) + pair) * DH * DH + idx];
        sctx[idx >> 6][idx & 63] = s;
    }

    const float* qbase = g_qkv + (size_t)b * NSEQ * N_QKV + h * DH;
    #pragma unroll
    for (int i = 0; i < 8; i++) {
        int id = tid + i * 256;
        int r  = id >> 4;
        int c  = (id & 15) * 4;
        *(float4*)&sq[r][c] =
            *(const float4*)(qbase + (size_t)(n0 + r) * N_QKV + c);
    }
    __syncthreads();

    const int e0 = (tid & 15) * 4;
    const int rg = tid >> 4;
    float acc[8][4];
    #pragma unroll
    for (int i = 0; i < 8; i++)
        #pragma unroll
        for (int j = 0; j < 4; j++) acc[i][j] = 0.f;

    #pragma unroll 8
    for (int d = 0; d < DH; d++) {
        float4 c4 = *(const float4*)&sctx[d][e0];
        float cv[4] = {c4.x, c4.y, c4.z, c4.w};
        #pragma unroll
        for (int i = 0; i < 8; i++) {
            float a = sq[rg + 16 * i][d];
            #pragma unroll
            for (int j = 0; j < 4; j++)
                acc[i][j] += a * cv[j];
        }
    }

    // tiled store: row = b*NSEQ + n0 + rg + 16*i, col = h*64 + e0 + j
    const int R0 = (b * NSEQ + n0) >> 4;          // + i
    const int S  = (h * DH + e0) >> 3;
    const int g2 = rg & 7;
    const int slot = (rg >> 3) + ((e0 & 4) ? 2 : 0);
    #pragma unroll
    for (int i = 0; i < 8; i++) {
        float* blk = g_attn + ((size_t)(R0 + i) * (INNER >> 3) + S) * 128;
        #pragma unroll
        for (int j = 0; j < 4; j++)
            blk[(g2 * 4 + j) * 4 + slot] = to_tf32(acc[i][j]);
    }
}

// ---------------------------------------------------------------------------
extern "C" void kernel_launch(void* const* d_in, const int* in_sizes, int n_in,
                              void* d_out, int out_size)
{
    const float* x     = (const float*)d_in[0];   // [4,4096,1024]
    const float* w_qkv = (const float*)d_in[1];   // [1536,1024]
    const float* w_out = (const float*)d_in[2];   // [1024,512]
    const float* b_out = (const float*)d_in[3];   // [1024]
    float* out = (float*)d_out;                   // [4,4096,1024]

    float *qkv_p, *attn_p, *xc_p, *wqkvc_p, *woutc_p;
    cudaGetSymbolAddress((void**)&qkv_p,   g_qkv);
    cudaGetSymbolAddress((void**)&attn_p,  g_attn);
    cudaGetSymbolAddress((void**)&xc_p,    g_xc);
    cudaGetSymbolAddress((void**)&wqkvc_p, g_wqkvc);
    cudaGetSymbolAddress((void**)&woutc_p, g_woutc);

    cudaFuncSetAttribute(tf32_gemm_mma<192>,
        cudaFuncAttributeMaxDynamicSharedMemorySize, SMEM_GEMM_N(192));
    cudaFuncSetAttribute(tf32_gemm_mma<128>,
        cudaFuncAttributeMaxDynamicSharedMemorySize, SMEM_GEMM_N(128));

    // 0) tile + round inputs to fragment-native tf32 layouts
    {
        int ta = (M_ROWS / 16) * (DIM / 8) * 32;
        tile_a_kernel<<<(ta + 255) / 256, 256>>>(x, xc_p, M_ROWS, DIM);
        int tb1 = (N_QKV / 8) * (DIM / 8) * 32;
        tile_b_kernel<<<(tb1 + 255) / 256, 256>>>(w_qkv, wqkvc_p, N_QKV, DIM);
        int tb2 = (DIM / 8) * (INNER / 8) * 32;
        tile_b_kernel<<<(tb2 + 255) / 256, 256>>>(w_out, woutc_p, DIM, INNER);
    }

    // 1) QKV projection: [16384,1536] = xc @ wqkvc^T  (1024 CTAs, ~6.9 waves)
    tf32_gemm_mma<192><<<dim3(N_QKV / 192, M_ROWS / 128), 256,
                         SMEM_GEMM_N(192)>>>(
        xc_p, wqkvc_p, qkv_p, nullptr, M_ROWS, N_QKV, DIM);

    // 2) softmax(k) + context partials
    ctx_kernel<<<dim3(B * HEADS, NCHUNK), 256>>>();

    // 3) q @ context -> attn (tiled tf32) [16384, 512]
    attn_kernel<<<dim3(B * HEADS, NSEQ / 128), 256>>>();

    // 4) output projection + bias (1024 CTAs, ~6.9 waves)
    tf32_gemm_mma<128><<<dim3(DIM / 128, M_ROWS / 128), 256,
                         SMEM_GEMM_N(128)>>>(
        attn_p, woutc_p, out, b_out, M_ROWS, DIM, INNER);
}